// round 9
// baseline (speedup 1.0000x reference)
#include <cuda_runtime.h>
#include <cuda_bf16.h>
#include <cstdint>

// Problem dims — FIXED by the dataset (reference hardcodes them).
#define N_NODES 100000
#define N_EDGES 1600000
#define IN_C    128
#define HID_C   128
#define OUT_C   40

#define CHUNK   16          // nodes per block iteration (100000 % 16 == 0)
#define FT      512         // threads in fused kernel (16 warps)
#define FGRID   304         // persistent grid (2 per SM on 152-SM GB300)

// ---------------- scratch (static __device__ globals; no allocation) --------
__device__ float g_t  [(size_t)N_NODES * OUT_C];   // 16 MB: layer-2 projected
__device__ int   g_degi[N_NODES];                  // in-degree
__device__ int   g_dego[N_NODES];                  // out-degree
__device__ float g_iso[N_NODES];                   // out-degree^{-1/2}
__device__ float g_isi[N_NODES];                   // in-degree^{-1/2}
__device__ int   g_src[N_EDGES];
__device__ int   g_dst[N_EDGES];
__device__ int   g_row[N_NODES];                   // CSR segment start (by dst)
__device__ int   g_cur[N_NODES];                   // fill cursors
__device__ int   g_eidx[N_EDGES];                  // CSR: src ids grouped by dst
__device__ int   g_mode;                           // edge dtype
__device__ int   g_total;                          // CSR allocation counter

// ---------------- dtype probe ------------------------------------------------
__global__ void k_detect(const int* __restrict__ w32) {
    if (blockIdx.x != 0 || threadIdx.x != 0) return;
    int oz = 0, ez = 0, ir = 0;
    for (int i = 0; i < 512; i++) {
        int w = w32[i];
        if (w == 0) { if (i & 1) oz++; else ez++; }
        if (w >= 0 && w < N_NODES) ir++;
    }
    int mode;
    if (oz > 240)      mode = 1;   // int64
    else if (ez > 240) mode = 3;   // float64
    else if (ir > 500) mode = 0;   // int32
    else               mode = 2;   // float32
    g_mode = mode;
}

// ---------------- zero + convert + degree histogram --------------------------
__global__ void k_zero_deg() {
    int i = blockIdx.x * blockDim.x + threadIdx.x;
    if (i < N_NODES) { g_degi[i] = 0; g_dego[i] = 0; }
    if (i == 0) g_total = 0;
}

__global__ void k_convert(const void* __restrict__ ei) {
    int i = blockIdx.x * blockDim.x + threadIdx.x;
    if (i >= 2 * N_EDGES) return;
    int mode = g_mode;
    long long v;
    if (mode == 1)      v = ((const long long*)ei)[i];
    else if (mode == 0) v = (long long)((const int*)ei)[i];
    else if (mode == 2) v = (long long)((const float*)ei)[i];
    else                v = (long long)((const double*)ei)[i];
    int vi = (int)v;
    if (vi < 0) vi = 0;
    if (vi >= N_NODES) vi = N_NODES - 1;
    if (i < N_EDGES) { g_src[i] = vi;           atomicAdd(&g_dego[vi], 1); }
    else             { g_dst[i - N_EDGES] = vi; atomicAdd(&g_degi[vi], 1); }
}

// ---------------- norms + CSR segment allocation (fused) ---------------------
__global__ void k_isqrt_alloc() {
    int i = blockIdx.x * blockDim.x + threadIdx.x;
    if (i >= N_NODES) return;
    g_iso[i] = rsqrtf((float)max(g_dego[i], 1));
    g_isi[i] = rsqrtf((float)max(g_degi[i], 1));
    int pos = atomicAdd(&g_total, g_degi[i]);
    g_row[i] = pos;
    g_cur[i] = pos;
}

__global__ void k_fill() {
    int e = blockIdx.x * blockDim.x + threadIdx.x;
    if (e >= N_EDGES) return;
    int d = g_dst[e];
    int pos = atomicAdd(&g_cur[d], 1);
    g_eidx[pos] = g_src[e];
}

// ---------------- FUSED: gather-x + GEMM1 + relu/norm + GEMM2 ---------------
// Per 16-node chunk:
//  A: warp w gathers xagg[w] = sum_{s in CSR[d]} iso[s]*x[s]  (swizzled k-major)
//  B: block GEMM1: h[n][col] = sum_k xagg[n][k]*W1[k][col], relu*iso*isi
//  C: warp w projects h[w] @ W2 -> g_t[d]
// xs swizzle: value of node n at row k lives in column n ^ ((k>>2)&15).
__global__ __launch_bounds__(FT, 2)
void k_fused(const float* __restrict__ x, const float* __restrict__ W1,
             const float* __restrict__ W2) {
    __shared__ __align__(16) float xs[IN_C * CHUNK];    // 8 KB, swizzled
    __shared__ __align__(16) float hs[CHUNK * HID_C];   // 8 KB, node-major
    __shared__ float W2s[HID_C * OUT_C];                // 20 KB
    __shared__ float scs[CHUNK];

    const int t = threadIdx.x;
    const int wid = t >> 5;
    const int lane = t & 31;

    // Load W2 once (5120 floats / 512 threads = 10 each, coalesced)
    #pragma unroll
    for (int i = 0; i < (HID_C * OUT_C) / FT; i++)
        W2s[i * FT + t] = W2[i * FT + t];
    __syncthreads();

    for (int base = blockIdx.x * CHUNK; base < N_NODES; base += FGRID * CHUNK) {
        // ---------------- Phase A: gather ----------------
        {
            const int d = base + wid;
            if (lane == 0) scs[wid] = g_iso[d] * g_isi[d];
            const int beg = g_row[d];
            const int end = beg + g_degi[d];
            float4 acc = make_float4(0.f, 0.f, 0.f, 0.f);
            for (int j = beg; j < end; j++) {
                int s = g_eidx[j];                       // warp-uniform
                float fs = g_iso[s];                     // warp-uniform
                float4 v = *((const float4*)(x + (size_t)s * IN_C) + lane);
                acc.x += v.x * fs; acc.y += v.y * fs;
                acc.z += v.z * fs; acc.w += v.w * fs;
            }
            // store swizzled: k = 4*lane + c, col' = wid ^ (lane & 15)
            const int colp = wid ^ (lane & 15);
            xs[(4 * lane + 0) * CHUNK + colp] = acc.x;
            xs[(4 * lane + 1) * CHUNK + colp] = acc.y;
            xs[(4 * lane + 2) * CHUNK + colp] = acc.z;
            xs[(4 * lane + 3) * CHUNK + colp] = acc.w;
        }
        __syncthreads();

        // ---------------- Phase B: GEMM1 + relu/norm ----------------
        {
            const int col = t & 127;
            const int a = t >> 7;               // node group 0..3 (nodes 4a..4a+3)
            float acc0 = 0.f, acc1 = 0.f, acc2 = 0.f, acc3 = 0.f;
            for (int k1 = 0; k1 < 8; k1++) {     // k = k1*16 + k2
                const int s1 = k1 & 3;           // high nibble of swizzle (address)
                const int blk = ((a ^ s1) << 2); // float4 block within row
                const float* __restrict__ wp = W1 + (size_t)(k1 * 16) * HID_C + col;
                const float* __restrict__ xp = xs + (k1 * 16) * CHUNK + blk;
                #pragma unroll
                for (int k2 = 0; k2 < 16; k2++) {
                    const int s0 = (k2 >> 2) & 3;         // compile-time
                    float4 f4 = *(const float4*)(xp + k2 * CHUNK);
                    float va[4] = {f4.x, f4.y, f4.z, f4.w};
                    float w = wp[(size_t)k2 * HID_C];     // LDG, L1-resident
                    acc0 += va[0 ^ s0] * w;
                    acc1 += va[1 ^ s0] * w;
                    acc2 += va[2 ^ s0] * w;
                    acc3 += va[3 ^ s0] * w;
                }
            }
            const int n0 = a * 4;
            hs[(n0 + 0) * HID_C + col] = fmaxf(acc0, 0.f) * scs[n0 + 0];
            hs[(n0 + 1) * HID_C + col] = fmaxf(acc1, 0.f) * scs[n0 + 1];
            hs[(n0 + 2) * HID_C + col] = fmaxf(acc2, 0.f) * scs[n0 + 2];
            hs[(n0 + 3) * HID_C + col] = fmaxf(acc3, 0.f) * scs[n0 + 3];
        }
        __syncthreads();

        // ---------------- Phase C: GEMM2 (per-warp, proven) ----------------
        {
            const int d = base + wid;
            const float* __restrict__ myhs = hs + wid * HID_C;
            float a0 = 0.f, a1 = 0.f;
            #pragma unroll 8
            for (int k4 = 0; k4 < HID_C / 4; k4++) {
                float4 h4 = *(const float4*)(myhs + k4 * 4);
                float hv[4] = {h4.x, h4.y, h4.z, h4.w};
                #pragma unroll
                for (int c = 0; c < 4; c++) {
                    int k = k4 * 4 + c;
                    a0 += hv[c] * W2s[k * OUT_C + lane];
                    if (lane < 8) a1 += hv[c] * W2s[k * OUT_C + 32 + lane];
                }
            }
            g_t[(size_t)d * OUT_C + lane] = a0;
            if (lane < 8) g_t[(size_t)d * OUT_C + 32 + lane] = a1;
        }
        // next Phase A runs only after the __syncthreads at top of next iter
        __syncthreads();
    }
}

// ---------------- gather 2: out[d] = isi[d] * sum g_t[s], 3 nodes/warp ------
__global__ __launch_bounds__(256)
void k_agg2(float* __restrict__ out) {
    int gw = (blockIdx.x * blockDim.x + threadIdx.x) >> 5;
    int lane = threadIdx.x & 31;
    int sub = lane / 10;                 // 0,1,2 (lanes 30,31 idle)
    int c = lane - sub * 10;             // float4 chunk 0..9
    int d = gw * 3 + sub;
    if (sub >= 3 || d >= N_NODES) return;
    int beg = g_row[d];
    int end = beg + g_degi[d];
    float4 acc = make_float4(0.f, 0.f, 0.f, 0.f);
    for (int j = beg; j < end; j++) {
        int s = g_eidx[j];
        float4 v = *reinterpret_cast<const float4*>(g_t + (size_t)s * OUT_C + c * 4);
        acc.x += v.x; acc.y += v.y; acc.z += v.z; acc.w += v.w;
    }
    float sc = g_isi[d];
    acc.x *= sc; acc.y *= sc; acc.z *= sc; acc.w *= sc;
    *reinterpret_cast<float4*>(out + (size_t)d * OUT_C + c * 4) = acc;
}

// ---------------- launch ----------------------------------------------------
extern "C" void kernel_launch(void* const* d_in, const int* in_sizes, int n_in,
                              void* d_out, int out_size) {
    const float* x  = (const float*)d_in[0];
    const void*  ei = d_in[1];
    const float* W1 = (const float*)d_in[2];
    const float* W2 = (const float*)d_in[3];
    float* out = (float*)d_out;

    // 0) dtype probe; zero degrees; convert + degree histogram (fused)
    k_detect<<<1, 32>>>((const int*)ei);
    k_zero_deg<<<(N_NODES + 255) / 256, 256>>>();
    k_convert<<<(2 * N_EDGES + 255) / 256, 256>>>(ei);

    // 1) norms + CSR segment allocation, then fill
    k_isqrt_alloc<<<(N_NODES + 255) / 256, 256>>>();
    k_fill<<<(N_EDGES + 255) / 256, 256>>>();

    // 2) FUSED gather-x + GEMM1 + relu/norm + GEMM2 (persistent)
    k_fused<<<FGRID, FT>>>(x, W1, W2);

    // 3) layer-2 aggregation + final scale into d_out (3 nodes per warp)
    {
        int warps = (N_NODES + 2) / 3;
        int blocks = (warps * 32 + 255) / 256;
        k_agg2<<<blocks, 256>>>(out);
    }
}

// round 10
// speedup vs baseline: 1.4084x; 1.4084x over previous
#include <cuda_runtime.h>
#include <cuda_bf16.h>
#include <cstdint>

// Problem dims — FIXED by the dataset (reference hardcodes them).
#define N_NODES 100000
#define N_EDGES 1600000
#define IN_C    128
#define HID_C   128
#define OUT_C   40

#define WPB     8     // warps per block in fused agg kernel
#define WPAD    136   // padded W1 row stride (floats) -> conflict-free B frags
#define GEMM1_BLOCKS ((N_NODES + 127) / 128)   // 782

// ---------------- scratch (static __device__ globals; no allocation) --------
__device__ float g_h1 [(size_t)N_NODES * HID_C];   // 51.2 MB
__device__ float g_t  [(size_t)N_NODES * OUT_C];   // 16 MB
__device__ int   g_degi[N_NODES];                  // in-degree
__device__ int   g_dego[N_NODES];                  // out-degree
__device__ float g_iso[N_NODES];                   // out-degree^{-1/2}
__device__ float g_isi[N_NODES];                   // in-degree^{-1/2}
__device__ int   g_src[N_EDGES];
__device__ int   g_dst[N_EDGES];
__device__ int   g_row[N_NODES];                   // CSR segment start (by dst)
__device__ int   g_cur[N_NODES];                   // fill cursors
__device__ int   g_eidx[N_EDGES];                  // CSR: src ids grouped by dst
__device__ int   g_mode;                           // edge dtype
__device__ int   g_total;                          // CSR allocation counter

// ---------------- helpers ----------------------------------------------------
__device__ __forceinline__ uint32_t f2tf32(float v) {
    uint32_t r;
    asm("cvt.rna.tf32.f32 %0, %1;" : "=r"(r) : "f"(v));
    return r;
}

// ---------------- dtype probe ------------------------------------------------
__global__ void k_detect(const int* __restrict__ w32) {
    if (blockIdx.x != 0 || threadIdx.x != 0) return;
    int oz = 0, ez = 0, ir = 0;
    for (int i = 0; i < 512; i++) {
        int w = w32[i];
        if (w == 0) { if (i & 1) oz++; else ez++; }
        if (w >= 0 && w < N_NODES) ir++;
    }
    int mode;
    if (oz > 240)      mode = 1;   // int64
    else if (ez > 240) mode = 3;   // float64
    else if (ir > 500) mode = 0;   // int32
    else               mode = 2;   // float32
    g_mode = mode;
}

// ---------------- zero + convert + degree histogram --------------------------
__global__ void k_zero_deg() {
    int i = blockIdx.x * blockDim.x + threadIdx.x;
    if (i < N_NODES) { g_degi[i] = 0; g_dego[i] = 0; }
    if (i == 0) g_total = 0;
}

__global__ void k_convert(const void* __restrict__ ei) {
    int i = blockIdx.x * blockDim.x + threadIdx.x;
    if (i >= 2 * N_EDGES) return;
    int mode = g_mode;
    long long v;
    if (mode == 1)      v = ((const long long*)ei)[i];
    else if (mode == 0) v = (long long)((const int*)ei)[i];
    else if (mode == 2) v = (long long)((const float*)ei)[i];
    else                v = (long long)((const double*)ei)[i];
    int vi = (int)v;
    if (vi < 0) vi = 0;
    if (vi >= N_NODES) vi = N_NODES - 1;
    if (i < N_EDGES) { g_src[i] = vi;           atomicAdd(&g_dego[vi], 1); }
    else             { g_dst[i - N_EDGES] = vi; atomicAdd(&g_degi[vi], 1); }
}

// ---------------- norms + CSR segment allocation (fused) ---------------------
__global__ void k_isqrt_alloc() {
    int i = blockIdx.x * blockDim.x + threadIdx.x;
    if (i >= N_NODES) return;
    g_iso[i] = rsqrtf((float)max(g_dego[i], 1));
    g_isi[i] = rsqrtf((float)max(g_degi[i], 1));
    int pos = atomicAdd(&g_total, g_degi[i]);
    g_row[i] = pos;
    g_cur[i] = pos;
}

__global__ void k_fill() {
    int e = blockIdx.x * blockDim.x + threadIdx.x;
    if (e >= N_EDGES) return;
    int d = g_dst[e];
    int pos = atomicAdd(&g_cur[d], 1);
    g_eidx[pos] = g_src[e];
}

// ---------------- GEMM1 (tf32 tensor core): h1 = (x*iso) @ W1 ---------------
// Block: 256 threads = 8 warps, each warp owns 16 rows; block tile 128x128.
// W1 staged in smem (tf32-rounded, WPAD=136 stride -> conflict-free B frags).
// mma.m16n8k8: per warp 16 k-steps x 16 n-tiles.
__global__ __launch_bounds__(256)
void k_gemm1_tf32(const float* __restrict__ x, const float* __restrict__ W) {
    extern __shared__ uint32_t Ws[];   // [128][WPAD] tf32 bits, 69.6 KB
    const int t = threadIdx.x;
    const int wid = t >> 5;
    const int lane = t & 31;

    // Stage W1 with round-to-nearest tf32 conversion (coalesced)
    #pragma unroll
    for (int i = 0; i < (IN_C * HID_C) / 256; i++) {
        int item = i * 256 + t;
        int kr = item >> 7, nc = item & 127;
        Ws[kr * WPAD + nc] = f2tf32(W[item]);
    }
    __syncthreads();

    const int row0 = blockIdx.x * 128 + wid * 16 + (lane >> 2);
    const int row1 = row0 + 8;
    const int rc0 = min(row0, N_NODES - 1);
    const int rc1 = min(row1, N_NODES - 1);
    const float iso0 = g_iso[rc0];
    const float iso1 = g_iso[rc1];
    const float* __restrict__ xr0 = x + (size_t)rc0 * IN_C + (lane & 3);
    const float* __restrict__ xr1 = x + (size_t)rc1 * IN_C + (lane & 3);

    float acc[16][4];
    #pragma unroll
    for (int n = 0; n < 16; n++)
        #pragma unroll
        for (int c = 0; c < 4; c++) acc[n][c] = 0.f;

    #pragma unroll 2
    for (int ks = 0; ks < 16; ks++) {
        const int k0 = ks * 8;
        // A fragment (row-major 16x8)
        uint32_t a0 = f2tf32(xr0[k0]     * iso0);
        uint32_t a1 = f2tf32(xr1[k0]     * iso1);
        uint32_t a2 = f2tf32(xr0[k0 + 4] * iso0);
        uint32_t a3 = f2tf32(xr1[k0 + 4] * iso1);
        const uint32_t* bb0 = Ws + (k0 + (lane & 3)) * WPAD + (lane >> 2);
        const uint32_t* bb1 = bb0 + 4 * WPAD;
        #pragma unroll
        for (int n = 0; n < 16; n++) {
            uint32_t b0 = bb0[n * 8];
            uint32_t b1 = bb1[n * 8];
            asm volatile(
                "mma.sync.aligned.m16n8k8.row.col.f32.tf32.tf32.f32 "
                "{%0,%1,%2,%3}, {%4,%5,%6,%7}, {%8,%9}, {%0,%1,%2,%3};"
                : "+f"(acc[n][0]), "+f"(acc[n][1]), "+f"(acc[n][2]), "+f"(acc[n][3])
                : "r"(a0), "r"(a1), "r"(a2), "r"(a3), "r"(b0), "r"(b1));
        }
    }

    // Epilogue: c0,c1 -> (row0, col..col+1); c2,c3 -> (row1, ...)
    const int colb = (lane & 3) * 2;
    #pragma unroll
    for (int n = 0; n < 16; n++) {
        int col = n * 8 + colb;
        if (row0 < N_NODES)
            *reinterpret_cast<float2*>(g_h1 + (size_t)row0 * HID_C + col) =
                make_float2(acc[n][0], acc[n][1]);
        if (row1 < N_NODES)
            *reinterpret_cast<float2*>(g_h1 + (size_t)row1 * HID_C + col) =
                make_float2(acc[n][2], acc[n][3]);
    }
}

// ---------------- FUSED: agg1 + relu/norm + GEMM2 (proven round 8) ----------
__global__ __launch_bounds__(WPB * 32)
void k_agg1_gemm2(const float* __restrict__ W2) {
    __shared__ float W2s[HID_C][OUT_C];            // 20 KB, loaded once
    __shared__ __align__(16) float as[WPB][HID_C]; // per-warp staged row

    const int t = threadIdx.x;
    #pragma unroll
    for (int i = 0; i < (HID_C * OUT_C) / (WPB * 32); i++) {
        int item = i * (WPB * 32) + t;
        ((float*)W2s)[item] = W2[item];
    }
    __syncthreads();

    const int wid = t >> 5;
    const int lane = t & 31;
    const int d = blockIdx.x * WPB + wid;
    if (d >= N_NODES) return;

    const int beg = g_row[d];
    const int end = beg + g_degi[d];
    float4 acc = make_float4(0.f, 0.f, 0.f, 0.f);
    for (int j = beg; j < end; j++) {
        int s = g_eidx[j];   // warp-uniform -> broadcast
        float4 v = *(reinterpret_cast<const float4*>(g_h1 + (size_t)s * HID_C) + lane);
        acc.x += v.x; acc.y += v.y; acc.z += v.z; acc.w += v.w;
    }
    const float sc = g_iso[d] * g_isi[d];
    acc.x = fmaxf(acc.x, 0.f) * sc;
    acc.y = fmaxf(acc.y, 0.f) * sc;
    acc.z = fmaxf(acc.z, 0.f) * sc;
    acc.w = fmaxf(acc.w, 0.f) * sc;
    *reinterpret_cast<float4*>(&as[wid][lane * 4]) = acc;
    __syncwarp();

    float acc0 = 0.f, acc1 = 0.f;
    #pragma unroll 8
    for (int k = 0; k < HID_C; k++) {
        float a = as[wid][k];
        acc0 += a * W2s[k][lane];
        if (lane < 8) acc1 += a * W2s[k][32 + lane];
    }
    g_t[(size_t)d * OUT_C + lane] = acc0;
    if (lane < 8) g_t[(size_t)d * OUT_C + 32 + lane] = acc1;
}

// ---------------- gather 2: out[d] = isi[d] * sum g_t[s], 3 nodes/warp ------
__global__ __launch_bounds__(256)
void k_agg2(float* __restrict__ out) {
    int gw = (blockIdx.x * blockDim.x + threadIdx.x) >> 5;
    int lane = threadIdx.x & 31;
    int sub = lane / 10;                 // 0,1,2 (lanes 30,31 idle)
    int c = lane - sub * 10;             // float4 chunk 0..9
    int d = gw * 3 + sub;
    if (sub >= 3 || d >= N_NODES) return;
    int beg = g_row[d];
    int end = beg + g_degi[d];
    float4 acc = make_float4(0.f, 0.f, 0.f, 0.f);
    for (int j = beg; j < end; j++) {
        int s = g_eidx[j];
        float4 v = *reinterpret_cast<const float4*>(g_t + (size_t)s * OUT_C + c * 4);
        acc.x += v.x; acc.y += v.y; acc.z += v.z; acc.w += v.w;
    }
    float sc = g_isi[d];
    acc.x *= sc; acc.y *= sc; acc.z *= sc; acc.w *= sc;
    *reinterpret_cast<float4*>(out + (size_t)d * OUT_C + c * 4) = acc;
}

// ---------------- launch ----------------------------------------------------
extern "C" void kernel_launch(void* const* d_in, const int* in_sizes, int n_in,
                              void* d_out, int out_size) {
    const float* x  = (const float*)d_in[0];
    const void*  ei = d_in[1];
    const float* W1 = (const float*)d_in[2];
    const float* W2 = (const float*)d_in[3];
    float* out = (float*)d_out;

    // 0) dtype probe; zero degrees; convert + degree histogram (fused)
    k_detect<<<1, 32>>>((const int*)ei);
    k_zero_deg<<<(N_NODES + 255) / 256, 256>>>();
    k_convert<<<(2 * N_EDGES + 255) / 256, 256>>>(ei);

    // 1) norms + CSR segment allocation, then fill
    k_isqrt_alloc<<<(N_NODES + 255) / 256, 256>>>();
    k_fill<<<(N_EDGES + 255) / 256, 256>>>();

    // 2) layer-1 projection on tf32 tensor cores
    {
        const int smem = IN_C * WPAD * 4;   // 69632 B
        static int cfg_done = 0;
        if (!cfg_done) {
            cudaFuncSetAttribute(k_gemm1_tf32,
                                 cudaFuncAttributeMaxDynamicSharedMemorySize, smem);
            cfg_done = 1;
        }
        k_gemm1_tf32<<<GEMM1_BLOCKS, 256, smem>>>(x, W1);
    }

    // 3) FUSED layer-1 aggregation + relu/norm + layer-2 projection
    k_agg1_gemm2<<<(N_NODES + WPB - 1) / WPB, WPB * 32>>>(W2);

    // 4) layer-2 aggregation + final scale into d_out (3 nodes per warp)
    {
        int warps = (N_NODES + 2) / 3;
        int blocks = (warps * 32 + 255) / 256;
        k_agg2<<<blocks, 256>>>(out);
    }
}